// round 15
// baseline (speedup 1.0000x reference)
#include <cuda_runtime.h>
#include <cstdint>

typedef unsigned long long ULL;

// ---------- packed fp32x2 helpers ----------
__device__ __forceinline__ void ffma2(ULL &d, ULL a, ULL b) {
    asm("fma.rn.f32x2 %0, %1, %2, %0;" : "+l"(d) : "l"(a), "l"(b));
}
__device__ __forceinline__ float2 unpack2(ULL v) {
    float2 f; asm("mov.b64 {%0,%1}, %2;" : "=f"(f.x), "=f"(f.y) : "l"(v)); return f;
}

// ---------- activations: single-MUFU tanh ----------
__device__ __forceinline__ float tanh_ap(float x) {
    float r; asm("tanh.approx.f32 %0, %1;" : "=f"(r) : "f"(x)); return r;
}
__device__ __forceinline__ float sig_ap(float x) {
    return fmaf(0.5f, tanh_ap(0.5f * x), 0.5f);
}

// ---------- fp16 ----------
__device__ __forceinline__ uint32_t f16x2of(float hi, float lo) {
    uint32_t r; asm("cvt.rn.f16x2.f32 %0, %1, %2;" : "=r"(r) : "f"(hi), "f"(lo));
    return r;
}
__device__ __forceinline__ uint16_t f16of(float x) {
    uint16_t r; asm("cvt.rn.f16.f32 %0, %1;" : "=h"(r) : "f"(x));
    return r;
}
__device__ __forceinline__ float f16_to_f32(uint16_t v) {
    float f; asm("cvt.f32.f16 %0, %1;" : "=f"(f) : "h"(v));
    return f;
}

// ---------- cp.async ----------
__device__ __forceinline__ void cp16(uint32_t dst_smem, const void* src) {
    asm volatile("cp.async.cg.shared.global [%0], [%1], 16;" :: "r"(dst_smem), "l"(src) : "memory");
}
__device__ __forceinline__ void cp8(uint32_t dst_smem, const void* src) {
    asm volatile("cp.async.ca.shared.global [%0], [%1], 8;" :: "r"(dst_smem), "l"(src) : "memory");
}
__device__ __forceinline__ void cp_commit() { asm volatile("cp.async.commit_group;"); }
__device__ __forceinline__ void cp_wait0()  { asm volatile("cp.async.wait_group 0;" ::: "memory"); }
__device__ __forceinline__ void cp_wait1()  { asm volatile("cp.async.wait_group 1;" ::: "memory"); }

// ---------- constants ----------
constexpr int B = 512, T = 512;
constexpr long BT = (long)B * T;

// ---------- scratch ----------
__device__ __align__(16) uint16_t g_h0h[BT * 128];   // layer-0 out fp16, NATURAL [b*T+t][k]
__device__ __align__(16) uint16_t g_xp1h[BT * 512];  // layer-1 preacts fp16 [b*T+t][n]
__device__ __align__(16) uint16_t g_Bth[512 * 128];  // Wih_l1 fp16 [n][k] (n = dir*256+row)
__device__ float g_pooled[B * 128];

// ---------- load-balance mapping: grid (148, 2); SM pairing via bid%148 ----
__device__ __forceinline__ bool map_big(int x, int dir) {
    return dir == 0 ? (x < 68) : (x >= 80);
}
__device__ __forceinline__ int map_b0(int x, int dir, bool big) {
    return dir == 0 ? (big ? x * 4 : 272 + (x - 68) * 3)
                    : (big ? 240 + (x - 80) * 4 : x * 3);
}

// =======================================================================
// Layer-0 biLSTM core (R5/R8-protected structure), templated on row count.
// h written directly as fp16 to natural-layout g_h0h.
// =======================================================================
template <int RCT>
__device__ __forceinline__ void l0_body(
    int dir, int b0, int tid,
    const float* __restrict__ x,
    const float* __restrict__ Wih, const float* __restrict__ Whh, const float* __restrict__ bb,
    float (&h_s)[2][4 * 64], float4 (&x_s)[2][4])
{
    const int u   = tid >> 2;
    const int g   = tid & 3;
    const int row = g * 64 + u;

    ULL w2[32];
    {
        const ULL* wp = (const ULL*)(Whh + row * 64);
        #pragma unroll
        for (int i = 0; i < 32; i++) w2[i] = wp[i];
    }
    const float4 wih = *(const float4*)(Wih + row * 4);
    const float bias = bb[row];

    const int lane = tid & 31;
    const int qb   = lane & ~3;

    for (int i = tid; i < RCT * 64; i += 256) h_s[0][i] = 0.f;
    if (tid < RCT) {
        const int t0 = dir ? (T - 1) : 0;
        x_s[0][tid] = *(const float4*)(x + ((long)(b0 + tid) * T + t0) * 4);
    }
    __syncthreads();

    float c[RCT];
    #pragma unroll
    for (int j = 0; j < RCT; j++) c[j] = 0.f;
    int p = 0;

    for (int s = 0; s < T; s++) {
        const int t = dir ? (T - 1 - s) : s;
        if (tid < RCT) {
            const int sn = (s + 1 < T) ? s + 1 : s;
            const int tn = dir ? (T - 1 - sn) : sn;
            x_s[p ^ 1][tid] = *(const float4*)(x + ((long)(b0 + tid) * T + tn) * 4);
        }

        float pre[RCT];
        #pragma unroll
        for (int j = 0; j < RCT; j++) {
            ULL a0 = 0, a1 = 0;
            const ulonglong2* h4 = (const ulonglong2*)(h_s[p] + j * 64);
            #pragma unroll
            for (int k = 0; k < 16; k++) {
                ulonglong2 hv = h4[k];
                ffma2(a0, w2[2 * k],     hv.x);
                ffma2(a1, w2[2 * k + 1], hv.y);
            }
            const float2 f0 = unpack2(a0), f1 = unpack2(a1);
            const float4 xv = x_s[p][j];
            pre[j] = f0.x + f0.y + f1.x + f1.y + bias
                   + wih.x * xv.x + wih.y * xv.y + wih.z * xv.z + wih.w * xv.w;
        }

        #pragma unroll
        for (int j = 0; j < RCT; j++) {
            const float act = (g == 2) ? tanh_ap(pre[j]) : sig_ap(pre[j]);
            const float iv = __shfl_sync(0xffffffffu, act, qb + 0);
            const float fv = __shfl_sync(0xffffffffu, act, qb + 1);
            const float gv = __shfl_sync(0xffffffffu, act, qb + 2);
            const float ov = __shfl_sync(0xffffffffu, act, qb + 3);
            c[j] = fmaf(fv, c[j], iv * gv);
            const float h = ov * tanh_ap(c[j]);
            if (g == 0) {
                h_s[p ^ 1][j * 64 + u] = h;
                g_h0h[((long)(b0 + j) * T + t) * 128 + dir * 64 + u] = f16of(h);
            }
        }
        p ^= 1;
        __syncthreads();
    }
}

__global__ __launch_bounds__(256, 2) void lstm_l0(
    const float* __restrict__ x,
    const float* __restrict__ Wih_f, const float* __restrict__ Whh_f, const float* __restrict__ b_f,
    const float* __restrict__ Wih_b, const float* __restrict__ Whh_b, const float* __restrict__ b_b)
{
    __shared__ __align__(16) float h_s[2][4 * 64];
    __shared__ __align__(16) float4 x_s[2][4];

    const int xw  = blockIdx.x;
    const int dir = blockIdx.y;
    const bool big = map_big(xw, dir);
    const int b0   = map_b0(xw, dir, big);
    const int tid = threadIdx.x;

    const float* Wih = dir ? Wih_b : Wih_f;
    const float* Whh = dir ? Whh_b : Whh_f;
    const float* bb  = dir ? b_b   : b_f;

    if (big) l0_body<4>(dir, b0, tid, x, Wih, Whh, bb, h_s, x_s);
    else     l0_body<3>(dir, b0, tid, x, Wih, Whh, bb, h_s, x_s);
}

// =======================================================================
// Prep: g_Bth[n][k] = fp16(Wih_l1[n&255][k])   (n = dir*256 + gate_row)
// =======================================================================
__global__ void prep_bth(const float* __restrict__ Wf, const float* __restrict__ Wb)
{
    const int idx = blockIdx.x * 512 + threadIdx.x;   // 65536
    const int n = idx >> 7, k = idx & 127;
    const float* W = (n & 256) ? Wb : Wf;
    g_Bth[idx] = f16of(W[(n & 255) * 128 + k]);
}

// =======================================================================
// xp1 GEMM via fp16 mma.sync.m16n8k16 (same rate as bf16, 8x the mantissa).
// A = g_h0h [m][k] fp16 (natural), B = g_Bth [n][k] fp16; both k-contiguous.
// Smem rows padded to KP=40 u16 (conflict-free). 3-stage cp.async, 4x32 K.
// grid (4, 2048) n-fast, blk 256, 2 CTAs/SM (60KB smem/CTA).
// =======================================================================
constexpr int KP = 40;
constexpr int SLAB_U16 = 128 * KP;
constexpr int STG_U16 = 2 * SLAB_U16;
constexpr int SMEM_GEMM = 3 * STG_U16 * 2;     // 61440 B

__global__ __launch_bounds__(256, 2) void gemm_xp1(
    const float* __restrict__ bias_f, const float* __restrict__ bias_b)
{
    extern __shared__ uint16_t smh[];   // [stage][{A,B}][128][KP]
    const uint32_t smB = (uint32_t)__cvta_generic_to_shared(smh);
    const int tid  = threadIdx.x;
    const int lane = tid & 31;
    const int wid  = tid >> 5;
    const int g    = lane >> 2;
    const int cc   = lane & 3;
    const int wm   = (wid & 3) * 32;
    const int wn   = (wid >> 2) * 64;
    const long m0 = (long)blockIdx.y * 128;
    const int  n0 = blockIdx.x * 128;

    float acc[2][8][4];
    #pragma unroll
    for (int i = 0; i < 2; i++)
        #pragma unroll
        for (int j = 0; j < 8; j++)
            #pragma unroll
            for (int q = 0; q < 4; q++) acc[i][j][q] = 0.f;

    auto load_slab = [&](int buf, int kc) {
        const uint32_t abase = smB + (uint32_t)(buf * STG_U16) * 2;
        const uint32_t bbase = abase + (uint32_t)SLAB_U16 * 2;
        #pragma unroll
        for (int i = 0; i < 2; i++) {
            const int e = tid + i * 256;
            const int r = e >> 2, pt = e & 3;
            cp16(abase + (uint32_t)(r * KP + pt * 8) * 2,
                 g_h0h + (m0 + r) * 128 + kc * 32 + pt * 8);
        }
        #pragma unroll
        for (int i = 0; i < 2; i++) {
            const int e = tid + i * 256;
            const int r = e >> 2, pt = e & 3;
            cp16(bbase + (uint32_t)(r * KP + pt * 8) * 2,
                 g_Bth + (long)(n0 + r) * 128 + kc * 32 + pt * 8);
        }
    };

    load_slab(0, 0); cp_commit();
    load_slab(1, 1); cp_commit();

    for (int kc = 0; kc < 4; kc++) {
        if (kc == 3) cp_wait0(); else cp_wait1();
        __syncthreads();
        if (kc + 2 < 4) { load_slab((kc + 2) % 3, kc + 2); cp_commit(); }

        const uint32_t* As = (const uint32_t*)(smh + (kc % 3) * STG_U16);   // row stride 20 u32
        const uint32_t* Bs = As + SLAB_U16 / 2;

        #pragma unroll
        for (int kk = 0; kk < 2; kk++) {
            const int ko = kk * 8 + cc;
            uint32_t a[2][4];
            #pragma unroll
            for (int i = 0; i < 2; i++) {
                const uint32_t* ap = As + (wm + 16 * i + g) * 20 + ko;
                a[i][0] = ap[0];
                a[i][1] = ap[8 * 20];
                a[i][2] = ap[4];
                a[i][3] = ap[8 * 20 + 4];
            }
            uint32_t b[8][2];
            #pragma unroll
            for (int j = 0; j < 8; j++) {
                const uint32_t* bp = Bs + (wn + j * 8 + g) * 20 + ko;
                b[j][0] = bp[0];
                b[j][1] = bp[4];
            }
            #pragma unroll
            for (int i = 0; i < 2; i++)
                #pragma unroll
                for (int j = 0; j < 8; j++) {
                    asm("mma.sync.aligned.m16n8k16.row.col.f32.f16.f16.f32 "
                        "{%0,%1,%2,%3}, {%4,%5,%6,%7}, {%8,%9}, {%0,%1,%2,%3};"
                        : "+f"(acc[i][j][0]), "+f"(acc[i][j][1]),
                          "+f"(acc[i][j][2]), "+f"(acc[i][j][3])
                        : "r"(a[i][0]), "r"(a[i][1]), "r"(a[i][2]), "r"(a[i][3]),
                          "r"(b[j][0]), "r"(b[j][1]));
                }
        }
    }

    // epilogue: + bias, pack f16x2, u32 stores
    const float* bp = (n0 & 256) ? bias_b : bias_f;
    float bn0[8], bn1[8];
    #pragma unroll
    for (int j = 0; j < 8; j++) {
        const int n = ((n0 & 255) + wn + 8 * j + cc * 2);
        bn0[j] = bp[n & 255];
        bn1[j] = bp[(n + 1) & 255];
    }
    #pragma unroll
    for (int i = 0; i < 2; i++) {
        const long mrow = m0 + wm + 16 * i + g;
        uint16_t* r0 = g_xp1h + mrow * 512;
        uint16_t* r1 = r0 + 8 * 512;
        #pragma unroll
        for (int j = 0; j < 8; j++) {
            const int n = n0 + wn + 8 * j + cc * 2;
            *(uint32_t*)(r0 + n) = f16x2of(acc[i][j][1] + bn1[j], acc[i][j][0] + bn0[j]);
            *(uint32_t*)(r1 + n) = f16x2of(acc[i][j][3] + bn1[j], acc[i][j][2] + bn0[j]);
        }
    }
}

// =======================================================================
// Layer-1 biLSTM core (R12-protected structure; xp fp16), templated rows.
// =======================================================================
template <int RCT>
__device__ __forceinline__ void l1_body(
    int dir, int b0, int tid,
    const float* __restrict__ Whh,
    float (&h_s)[2][4 * 64], uint16_t (&xp_s)[2][4][4][72])
{
    const int u   = tid >> 2;
    const int g   = tid & 3;
    const int row = g * 64 + u;

    ULL w2[32];
    {
        const ULL* wp = (const ULL*)(Whh + row * 64);
        #pragma unroll
        for (int i = 0; i < 32; i++) w2[i] = wp[i];
    }
    const int lane = tid & 31;
    const int qb   = lane & ~3;

    const int j_st  = tid >> 6;
    const int c_st  = tid & 63;
    const int g_st  = c_st >> 4;
    const int u4_st = (c_st & 15) * 4;
    const uint32_t xpsB = (uint32_t)__cvta_generic_to_shared(&xp_s[0][0][0][0]);
    const uint32_t st_off = (uint32_t)(((j_st * 4 + g_st) * 72 + u4_st) * 2);
    const uint32_t buf_stride = (uint32_t)(4 * 4 * 72 * 2);
    const uint16_t* xp_src = g_xp1h + (long)(b0 + j_st) * T * 512 + dir * 256 + g_st * 64 + u4_st;
    const bool do_st = (j_st < RCT);

    for (int i = tid; i < RCT * 64; i += 256) h_s[0][i] = 0.f;

    float c[RCT], hsum[RCT];
    #pragma unroll
    for (int j = 0; j < RCT; j++) { c[j] = 0.f; hsum[j] = 0.f; }
    {
        const int t0 = dir ? (T - 1) : 0;
        if (do_st) cp8(xpsB + st_off, xp_src + (long)t0 * 512);
        cp_commit();
        cp_wait0();
    }
    __syncthreads();

    int p = 0;
    for (int s = 0; s < T; s++) {
        if (s + 1 < T) {
            const int tn = dir ? (T - 2 - s) : (s + 1);
            if (do_st) cp8(xpsB + (p ^ 1) * buf_stride + st_off, xp_src + (long)tn * 512);
            cp_commit();
        }

        float pre[RCT];
        #pragma unroll
        for (int j = 0; j < RCT; j++) {
            ULL a0 = 0, a1 = 0;
            const ulonglong2* h4 = (const ulonglong2*)(h_s[p] + j * 64);
            #pragma unroll
            for (int k = 0; k < 16; k++) {
                ulonglong2 hv = h4[k];
                ffma2(a0, w2[2 * k],     hv.x);
                ffma2(a1, w2[2 * k + 1], hv.y);
            }
            const float2 f0 = unpack2(a0), f1 = unpack2(a1);
            pre[j] = f0.x + f0.y + f1.x + f1.y + f16_to_f32(xp_s[p][j][g][u]);
        }

        #pragma unroll
        for (int j = 0; j < RCT; j++) {
            const float act = (g == 2) ? tanh_ap(pre[j]) : sig_ap(pre[j]);
            const float iv = __shfl_sync(0xffffffffu, act, qb + 0);
            const float fv = __shfl_sync(0xffffffffu, act, qb + 1);
            const float gv = __shfl_sync(0xffffffffu, act, qb + 2);
            const float ov = __shfl_sync(0xffffffffu, act, qb + 3);
            c[j] = fmaf(fv, c[j], iv * gv);
            const float h = ov * tanh_ap(c[j]);
            hsum[j] += h;
            if (g == 0) h_s[p ^ 1][j * 64 + u] = h;
        }
        cp_wait0();
        p ^= 1;
        __syncthreads();
    }

    if (g == 0) {
        #pragma unroll
        for (int j = 0; j < RCT; j++)
            g_pooled[(b0 + j) * 128 + dir * 64 + u] = hsum[j];
    }
}

__global__ __launch_bounds__(256, 2) void lstm_l1(
    const float* __restrict__ Whh_f, const float* __restrict__ Whh_b)
{
    __shared__ __align__(16) float h_s[2][4 * 64];
    __shared__ __align__(16) uint16_t xp_s[2][4][4][72];

    const int xw  = blockIdx.x;
    const int dir = blockIdx.y;
    const bool big = map_big(xw, dir);
    const int b0   = map_b0(xw, dir, big);
    const int tid = threadIdx.x;
    const float* Whh = dir ? Whh_b : Whh_f;

    if (big) l1_body<4>(dir, b0, tid, Whh, h_s, xp_s);
    else     l1_body<3>(dir, b0, tid, Whh, h_s, xp_s);
}

// =======================================================================
__global__ void fc_kernel(const float* __restrict__ fcw, const float* __restrict__ fcb,
                          float* __restrict__ out)
{
    const int gw   = (blockIdx.x * blockDim.x + threadIdx.x) >> 5;
    const int lane = threadIdx.x & 31;
    if (gw >= B) return;
    float sum = 0.f;
    #pragma unroll
    for (int qq = 0; qq < 4; qq++)
        sum += g_pooled[gw * 128 + qq * 32 + lane] * fcw[qq * 32 + lane];
    #pragma unroll
    for (int o = 16; o; o >>= 1) sum += __shfl_xor_sync(0xffffffffu, sum, o);
    if (lane == 0) out[gw] = sum * (1.f / 512.f) + fcb[0];
}

// =======================================================================
extern "C" void kernel_launch(void* const* d_in, const int* in_sizes, int n_in,
                              void* d_out, int out_size)
{
    const float* x     = (const float*)d_in[0];
    const float* Wih0f = (const float*)d_in[1];
    const float* Whh0f = (const float*)d_in[2];
    const float* b0f   = (const float*)d_in[3];
    const float* Wih0b = (const float*)d_in[4];
    const float* Whh0b = (const float*)d_in[5];
    const float* b0b   = (const float*)d_in[6];
    const float* Wih1f = (const float*)d_in[7];
    const float* Whh1f = (const float*)d_in[8];
    const float* b1f   = (const float*)d_in[9];
    const float* Wih1b = (const float*)d_in[10];
    const float* Whh1b = (const float*)d_in[11];
    const float* b1b   = (const float*)d_in[12];
    const float* fcw   = (const float*)d_in[13];
    const float* fcb   = (const float*)d_in[14];

    prep_bth<<<128, 512>>>(Wih1f, Wih1b);
    lstm_l0<<<dim3(148, 2), 256>>>(x, Wih0f, Whh0f, b0f, Wih0b, Whh0b, b0b);
    cudaFuncSetAttribute(gemm_xp1, cudaFuncAttributeMaxDynamicSharedMemorySize, SMEM_GEMM);
    gemm_xp1<<<dim3(4, 2048), 256, SMEM_GEMM>>>(b1f, b1b);
    lstm_l1<<<dim3(148, 2), 256>>>(Whh1f, Whh1b);
    fc_kernel<<<32, 512>>>(fcw, fcb, (float*)d_out);
}

// round 16
// speedup vs baseline: 1.1310x; 1.1310x over previous
#include <cuda_runtime.h>
#include <cstdint>

typedef unsigned long long ULL;

// ---------- packed fp32x2 helpers ----------
__device__ __forceinline__ void ffma2(ULL &d, ULL a, ULL b) {
    asm("fma.rn.f32x2 %0, %1, %2, %0;" : "+l"(d) : "l"(a), "l"(b));
}
__device__ __forceinline__ float2 unpack2(ULL v) {
    float2 f; asm("mov.b64 {%0,%1}, %2;" : "=f"(f.x), "=f"(f.y) : "l"(v)); return f;
}

// ---------- activations: single-MUFU tanh ----------
__device__ __forceinline__ float tanh_ap(float x) {
    float r; asm("tanh.approx.f32 %0, %1;" : "=f"(r) : "f"(x)); return r;
}
__device__ __forceinline__ float sig_ap(float x) {
    return fmaf(0.5f, tanh_ap(0.5f * x), 0.5f);
}

// ---------- fp16 ----------
__device__ __forceinline__ uint32_t f16x2of(float hi, float lo) {
    uint32_t r; asm("cvt.rn.f16x2.f32 %0, %1, %2;" : "=r"(r) : "f"(hi), "f"(lo));
    return r;
}
__device__ __forceinline__ uint16_t f16of(float x) {
    uint16_t r; asm("cvt.rn.f16.f32 %0, %1;" : "=h"(r) : "f"(x));
    return r;
}
__device__ __forceinline__ float f16_to_f32(uint16_t v) {
    float f; asm("cvt.f32.f16 %0, %1;" : "=f"(f) : "h"(v));
    return f;
}

// ---------- cp.async ----------
__device__ __forceinline__ void cp16(uint32_t dst_smem, const void* src) {
    asm volatile("cp.async.cg.shared.global [%0], [%1], 16;" :: "r"(dst_smem), "l"(src) : "memory");
}
__device__ __forceinline__ void cp8(uint32_t dst_smem, const void* src) {
    asm volatile("cp.async.ca.shared.global [%0], [%1], 8;" :: "r"(dst_smem), "l"(src) : "memory");
}
__device__ __forceinline__ void cp_commit() { asm volatile("cp.async.commit_group;"); }
__device__ __forceinline__ void cp_wait0()  { asm volatile("cp.async.wait_group 0;" ::: "memory"); }
__device__ __forceinline__ void cp_wait1()  { asm volatile("cp.async.wait_group 1;" ::: "memory"); }

// ---------- constants ----------
constexpr int B = 512, T = 512;
constexpr long BT = (long)B * T;
constexpr int HR = 72;             // h_s row stride (halves at +0 and +36: +4 banks)

// h position within padded row: k-low [0,32) at +u, k-high [32,64) at +4+u
__device__ __forceinline__ int hoff(int u) { return u + ((u >> 5) << 2); }

// ---------- scratch ----------
__device__ __align__(16) uint16_t g_h0h[BT * 128];   // layer-0 out fp16, NATURAL [b*T+t][k]
__device__ __align__(16) uint16_t g_xp1h[BT * 512];  // layer-1 preacts fp16 [b*T+t][n]
__device__ __align__(16) uint16_t g_Bth[512 * 128];  // Wih_l1 fp16 [n][k]
__device__ float g_pooled[B * 128];

// ---------- load-balance mapping: grid (148, 2); SM pairing via bid%148 ----
__device__ __forceinline__ bool map_big(int x, int dir) {
    return dir == 0 ? (x < 68) : (x >= 80);
}
__device__ __forceinline__ int map_b0(int x, int dir, bool big) {
    return dir == 0 ? (big ? x * 4 : 272 + (x - 68) * 3)
                    : (big ? 240 + (x - 80) * 4 : x * 3);
}

// =======================================================================
// Layer-0 biLSTM core: 2-way k-split dot (half the LDS), 1-shfl pair merge.
// Lane (u,g): loads k-half (g&1) of h, computes BOTH gate rows of its pair
// {g&~1, g|1} over that half; shfl.xor(1) completes the dots.
// =======================================================================
template <int RCT>
__device__ __forceinline__ void l0_body(
    int dir, int b0, int tid,
    const float* __restrict__ x,
    const float* __restrict__ Wih, const float* __restrict__ Whh, const float* __restrict__ bb,
    float (&h_s)[2][4 * HR], float4 (&x_s)[2][4])
{
    const int u   = tid >> 2;
    const int g   = tid & 3;
    const int row = g * 64 + u;
    const int kh  = g & 1;
    const int gp  = g & ~1;

    // weights: both pair gate-rows, own k-half (16+16 ULL = 64 regs, same as before)
    ULL wA[16], wB[16];
    {
        const ULL* wpA = (const ULL*)(Whh + (gp * 64 + u) * 64 + kh * 32);
        const ULL* wpB = (const ULL*)(Whh + ((gp + 1) * 64 + u) * 64 + kh * 32);
        #pragma unroll
        for (int i = 0; i < 16; i++) { wA[i] = wpA[i]; wB[i] = wpB[i]; }
    }
    const float4 wih = *(const float4*)(Wih + row * 4);
    const float bias = bb[row];

    const int lane = tid & 31;
    const int qb   = lane & ~3;

    for (int i = tid; i < RCT * HR; i += 256) h_s[0][i] = 0.f;
    if (tid < RCT) {
        const int t0 = dir ? (T - 1) : 0;
        x_s[0][tid] = *(const float4*)(x + ((long)(b0 + tid) * T + t0) * 4);
    }
    __syncthreads();

    float c[RCT];
    #pragma unroll
    for (int j = 0; j < RCT; j++) c[j] = 0.f;
    int p = 0;

    for (int s = 0; s < T; s++) {
        const int t = dir ? (T - 1 - s) : s;
        if (tid < RCT) {
            const int sn = (s + 1 < T) ? s + 1 : s;
            const int tn = dir ? (T - 1 - sn) : sn;
            x_s[p ^ 1][tid] = *(const float4*)(x + ((long)(b0 + tid) * T + tn) * 4);
        }

        float pre[RCT];
        #pragma unroll
        for (int j = 0; j < RCT; j++) {
            const ulonglong2* h4 = (const ulonglong2*)(h_s[p] + j * HR + kh * 36);
            ULL a = 0, b = 0;
            #pragma unroll
            for (int k = 0; k < 8; k++) {
                ulonglong2 hv = h4[k];
                ffma2(a, wA[2 * k],     hv.x);
                ffma2(a, wA[2 * k + 1], hv.y);
                ffma2(b, wB[2 * k],     hv.x);
                ffma2(b, wB[2 * k + 1], hv.y);
            }
            const float2 fa = unpack2(a), fb = unpack2(b);
            const float pA = fa.x + fa.y, pB = fb.x + fb.y;
            const float own   = kh ? pB : pA;
            const float other = kh ? pA : pB;
            const float recv  = __shfl_xor_sync(0xffffffffu, other, 1);
            const float4 xv = x_s[p][j];
            pre[j] = own + recv + bias
                   + wih.x * xv.x + wih.y * xv.y + wih.z * xv.z + wih.w * xv.w;
        }

        #pragma unroll
        for (int j = 0; j < RCT; j++) {
            const float act = (g == 2) ? tanh_ap(pre[j]) : sig_ap(pre[j]);
            const float iv = __shfl_sync(0xffffffffu, act, qb + 0);
            const float fv = __shfl_sync(0xffffffffu, act, qb + 1);
            const float gv = __shfl_sync(0xffffffffu, act, qb + 2);
            const float ov = __shfl_sync(0xffffffffu, act, qb + 3);
            c[j] = fmaf(fv, c[j], iv * gv);
            const float h = ov * tanh_ap(c[j]);
            if (g == 0) {
                h_s[p ^ 1][j * HR + hoff(u)] = h;
                g_h0h[((long)(b0 + j) * T + t) * 128 + dir * 64 + u] = f16of(h);
            }
        }
        p ^= 1;
        __syncthreads();
    }
}

__global__ __launch_bounds__(256, 2) void lstm_l0(
    const float* __restrict__ x,
    const float* __restrict__ Wih_f, const float* __restrict__ Whh_f, const float* __restrict__ b_f,
    const float* __restrict__ Wih_b, const float* __restrict__ Whh_b, const float* __restrict__ b_b)
{
    __shared__ __align__(16) float h_s[2][4 * HR];
    __shared__ __align__(16) float4 x_s[2][4];

    const int xw  = blockIdx.x;
    const int dir = blockIdx.y;
    const bool big = map_big(xw, dir);
    const int b0   = map_b0(xw, dir, big);
    const int tid = threadIdx.x;

    const float* Wih = dir ? Wih_b : Wih_f;
    const float* Whh = dir ? Whh_b : Whh_f;
    const float* bb  = dir ? b_b   : b_f;

    if (big) l0_body<4>(dir, b0, tid, x, Wih, Whh, bb, h_s, x_s);
    else     l0_body<3>(dir, b0, tid, x, Wih, Whh, bb, h_s, x_s);
}

// =======================================================================
// Prep: g_Bth[n][k] = fp16(Wih_l1[n&255][k])   (n = dir*256 + gate_row)
// =======================================================================
__global__ void prep_bth(const float* __restrict__ Wf, const float* __restrict__ Wb)
{
    const int idx = blockIdx.x * 512 + threadIdx.x;   // 65536
    const int n = idx >> 7, k = idx & 127;
    const float* W = (n & 256) ? Wb : Wf;
    g_Bth[idx] = f16of(W[(n & 255) * 128 + k]);
}

// =======================================================================
// xp1 GEMM via fp16 mma.sync.m16n8k16 (R15-exact, PROTECTED).
// grid (4, 2048) n-fast, blk 256, 2 CTAs/SM (60KB smem/CTA).
// =======================================================================
constexpr int KP = 40;
constexpr int SLAB_U16 = 128 * KP;
constexpr int STG_U16 = 2 * SLAB_U16;
constexpr int SMEM_GEMM = 3 * STG_U16 * 2;     // 61440 B

__global__ __launch_bounds__(256, 2) void gemm_xp1(
    const float* __restrict__ bias_f, const float* __restrict__ bias_b)
{
    extern __shared__ uint16_t smh[];   // [stage][{A,B}][128][KP]
    const uint32_t smB = (uint32_t)__cvta_generic_to_shared(smh);
    const int tid  = threadIdx.x;
    const int lane = tid & 31;
    const int wid  = tid >> 5;
    const int g    = lane >> 2;
    const int cc   = lane & 3;
    const int wm   = (wid & 3) * 32;
    const int wn   = (wid >> 2) * 64;
    const long m0 = (long)blockIdx.y * 128;
    const int  n0 = blockIdx.x * 128;

    float acc[2][8][4];
    #pragma unroll
    for (int i = 0; i < 2; i++)
        #pragma unroll
        for (int j = 0; j < 8; j++)
            #pragma unroll
            for (int q = 0; q < 4; q++) acc[i][j][q] = 0.f;

    auto load_slab = [&](int buf, int kc) {
        const uint32_t abase = smB + (uint32_t)(buf * STG_U16) * 2;
        const uint32_t bbase = abase + (uint32_t)SLAB_U16 * 2;
        #pragma unroll
        for (int i = 0; i < 2; i++) {
            const int e = tid + i * 256;
            const int r = e >> 2, pt = e & 3;
            cp16(abase + (uint32_t)(r * KP + pt * 8) * 2,
                 g_h0h + (m0 + r) * 128 + kc * 32 + pt * 8);
        }
        #pragma unroll
        for (int i = 0; i < 2; i++) {
            const int e = tid + i * 256;
            const int r = e >> 2, pt = e & 3;
            cp16(bbase + (uint32_t)(r * KP + pt * 8) * 2,
                 g_Bth + (long)(n0 + r) * 128 + kc * 32 + pt * 8);
        }
    };

    load_slab(0, 0); cp_commit();
    load_slab(1, 1); cp_commit();

    for (int kc = 0; kc < 4; kc++) {
        if (kc == 3) cp_wait0(); else cp_wait1();
        __syncthreads();
        if (kc + 2 < 4) { load_slab((kc + 2) % 3, kc + 2); cp_commit(); }

        const uint32_t* As = (const uint32_t*)(smh + (kc % 3) * STG_U16);   // row stride 20 u32
        const uint32_t* Bs = As + SLAB_U16 / 2;

        #pragma unroll
        for (int kk = 0; kk < 2; kk++) {
            const int ko = kk * 8 + cc;
            uint32_t a[2][4];
            #pragma unroll
            for (int i = 0; i < 2; i++) {
                const uint32_t* ap = As + (wm + 16 * i + g) * 20 + ko;
                a[i][0] = ap[0];
                a[i][1] = ap[8 * 20];
                a[i][2] = ap[4];
                a[i][3] = ap[8 * 20 + 4];
            }
            uint32_t b[8][2];
            #pragma unroll
            for (int j = 0; j < 8; j++) {
                const uint32_t* bp = Bs + (wn + j * 8 + g) * 20 + ko;
                b[j][0] = bp[0];
                b[j][1] = bp[4];
            }
            #pragma unroll
            for (int i = 0; i < 2; i++)
                #pragma unroll
                for (int j = 0; j < 8; j++) {
                    asm("mma.sync.aligned.m16n8k16.row.col.f32.f16.f16.f32 "
                        "{%0,%1,%2,%3}, {%4,%5,%6,%7}, {%8,%9}, {%0,%1,%2,%3};"
                        : "+f"(acc[i][j][0]), "+f"(acc[i][j][1]),
                          "+f"(acc[i][j][2]), "+f"(acc[i][j][3])
                        : "r"(a[i][0]), "r"(a[i][1]), "r"(a[i][2]), "r"(a[i][3]),
                          "r"(b[j][0]), "r"(b[j][1]));
                }
        }
    }

    const float* bp = (n0 & 256) ? bias_b : bias_f;
    float bn0[8], bn1[8];
    #pragma unroll
    for (int j = 0; j < 8; j++) {
        const int n = ((n0 & 255) + wn + 8 * j + cc * 2);
        bn0[j] = bp[n & 255];
        bn1[j] = bp[(n + 1) & 255];
    }
    #pragma unroll
    for (int i = 0; i < 2; i++) {
        const long mrow = m0 + wm + 16 * i + g;
        uint16_t* r0 = g_xp1h + mrow * 512;
        uint16_t* r1 = r0 + 8 * 512;
        #pragma unroll
        for (int j = 0; j < 8; j++) {
            const int n = n0 + wn + 8 * j + cc * 2;
            *(uint32_t*)(r0 + n) = f16x2of(acc[i][j][1] + bn1[j], acc[i][j][0] + bn0[j]);
            *(uint32_t*)(r1 + n) = f16x2of(acc[i][j][3] + bn1[j], acc[i][j][2] + bn0[j]);
        }
    }
}

// =======================================================================
// Layer-1 biLSTM core: same 2-way k-split dot; xp fp16 staged via cp.async.
// =======================================================================
template <int RCT>
__device__ __forceinline__ void l1_body(
    int dir, int b0, int tid,
    const float* __restrict__ Whh,
    float (&h_s)[2][4 * HR], uint16_t (&xp_s)[2][4][4][72])
{
    const int u   = tid >> 2;
    const int g   = tid & 3;
    const int kh  = g & 1;
    const int gp  = g & ~1;

    ULL wA[16], wB[16];
    {
        const ULL* wpA = (const ULL*)(Whh + (gp * 64 + u) * 64 + kh * 32);
        const ULL* wpB = (const ULL*)(Whh + ((gp + 1) * 64 + u) * 64 + kh * 32);
        #pragma unroll
        for (int i = 0; i < 16; i++) { wA[i] = wpA[i]; wB[i] = wpB[i]; }
    }
    const int lane = tid & 31;
    const int qb   = lane & ~3;

    const int j_st  = tid >> 6;
    const int c_st  = tid & 63;
    const int g_st  = c_st >> 4;
    const int u4_st = (c_st & 15) * 4;
    const uint32_t xpsB = (uint32_t)__cvta_generic_to_shared(&xp_s[0][0][0][0]);
    const uint32_t st_off = (uint32_t)(((j_st * 4 + g_st) * 72 + u4_st) * 2);
    const uint32_t buf_stride = (uint32_t)(4 * 4 * 72 * 2);
    const uint16_t* xp_src = g_xp1h + (long)(b0 + j_st) * T * 512 + dir * 256 + g_st * 64 + u4_st;
    const bool do_st = (j_st < RCT);

    for (int i = tid; i < RCT * HR; i += 256) h_s[0][i] = 0.f;

    float c[RCT], hsum[RCT];
    #pragma unroll
    for (int j = 0; j < RCT; j++) { c[j] = 0.f; hsum[j] = 0.f; }
    {
        const int t0 = dir ? (T - 1) : 0;
        if (do_st) cp8(xpsB + st_off, xp_src + (long)t0 * 512);
        cp_commit();
        cp_wait0();
    }
    __syncthreads();

    int p = 0;
    for (int s = 0; s < T; s++) {
        if (s + 1 < T) {
            const int tn = dir ? (T - 2 - s) : (s + 1);
            if (do_st) cp8(xpsB + (p ^ 1) * buf_stride + st_off, xp_src + (long)tn * 512);
            cp_commit();
        }

        float pre[RCT];
        #pragma unroll
        for (int j = 0; j < RCT; j++) {
            const ulonglong2* h4 = (const ulonglong2*)(h_s[p] + j * HR + kh * 36);
            ULL a = 0, b = 0;
            #pragma unroll
            for (int k = 0; k < 8; k++) {
                ulonglong2 hv = h4[k];
                ffma2(a, wA[2 * k],     hv.x);
                ffma2(a, wA[2 * k + 1], hv.y);
                ffma2(b, wB[2 * k],     hv.x);
                ffma2(b, wB[2 * k + 1], hv.y);
            }
            const float2 fa = unpack2(a), fb = unpack2(b);
            const float pA = fa.x + fa.y, pB = fb.x + fb.y;
            const float own   = kh ? pB : pA;
            const float other = kh ? pA : pB;
            const float recv  = __shfl_xor_sync(0xffffffffu, other, 1);
            pre[j] = own + recv + f16_to_f32(xp_s[p][j][g][u]);
        }

        #pragma unroll
        for (int j = 0; j < RCT; j++) {
            const float act = (g == 2) ? tanh_ap(pre[j]) : sig_ap(pre[j]);
            const float iv = __shfl_sync(0xffffffffu, act, qb + 0);
            const float fv = __shfl_sync(0xffffffffu, act, qb + 1);
            const float gv = __shfl_sync(0xffffffffu, act, qb + 2);
            const float ov = __shfl_sync(0xffffffffu, act, qb + 3);
            c[j] = fmaf(fv, c[j], iv * gv);
            const float h = ov * tanh_ap(c[j]);
            hsum[j] += h;
            if (g == 0) h_s[p ^ 1][j * HR + hoff(u)] = h;
        }
        cp_wait0();
        p ^= 1;
        __syncthreads();
    }

    if (g == 0) {
        #pragma unroll
        for (int j = 0; j < RCT; j++)
            g_pooled[(b0 + j) * 128 + dir * 64 + u] = hsum[j];
    }
}

__global__ __launch_bounds__(256, 2) void lstm_l1(
    const float* __restrict__ Whh_f, const float* __restrict__ Whh_b)
{
    __shared__ __align__(16) float h_s[2][4 * HR];
    __shared__ __align__(16) uint16_t xp_s[2][4][4][72];

    const int xw  = blockIdx.x;
    const int dir = blockIdx.y;
    const bool big = map_big(xw, dir);
    const int b0   = map_b0(xw, dir, big);
    const int tid = threadIdx.x;
    const float* Whh = dir ? Whh_b : Whh_f;

    if (big) l1_body<4>(dir, b0, tid, Whh, h_s, xp_s);
    else     l1_body<3>(dir, b0, tid, Whh, h_s, xp_s);
}

// =======================================================================
__global__ void fc_kernel(const float* __restrict__ fcw, const float* __restrict__ fcb,
                          float* __restrict__ out)
{
    const int gw   = (blockIdx.x * blockDim.x + threadIdx.x) >> 5;
    const int lane = threadIdx.x & 31;
    if (gw >= B) return;
    float sum = 0.f;
    #pragma unroll
    for (int qq = 0; qq < 4; qq++)
        sum += g_pooled[gw * 128 + qq * 32 + lane] * fcw[qq * 32 + lane];
    #pragma unroll
    for (int o = 16; o; o >>= 1) sum += __shfl_xor_sync(0xffffffffu, sum, o);
    if (lane == 0) out[gw] = sum * (1.f / 512.f) + fcb[0];
}

// =======================================================================
extern "C" void kernel_launch(void* const* d_in, const int* in_sizes, int n_in,
                              void* d_out, int out_size)
{
    const float* x     = (const float*)d_in[0];
    const float* Wih0f = (const float*)d_in[1];
    const float* Whh0f = (const float*)d_in[2];
    const float* b0f   = (const float*)d_in[3];
    const float* Wih0b = (const float*)d_in[4];
    const float* Whh0b = (const float*)d_in[5];
    const float* b0b   = (const float*)d_in[6];
    const float* Wih1f = (const float*)d_in[7];
    const float* Whh1f = (const float*)d_in[8];
    const float* b1f   = (const float*)d_in[9];
    const float* Wih1b = (const float*)d_in[10];
    const float* Whh1b = (const float*)d_in[11];
    const float* b1b   = (const float*)d_in[12];
    const float* fcw   = (const float*)d_in[13];
    const float* fcb   = (const float*)d_in[14];

    prep_bth<<<128, 512>>>(Wih1f, Wih1b);
    lstm_l0<<<dim3(148, 2), 256>>>(x, Wih0f, Whh0f, b0f, Wih0b, Whh0b, b0b);
    cudaFuncSetAttribute(gemm_xp1, cudaFuncAttributeMaxDynamicSharedMemorySize, SMEM_GEMM);
    gemm_xp1<<<dim3(4, 2048), 256, SMEM_GEMM>>>(b1f, b1b);
    lstm_l1<<<dim3(148, 2), 256>>>(Whh1f, Whh1b);
    fc_kernel<<<32, 512>>>(fcw, fcb, (float*)d_out);
}